// round 15
// baseline (speedup 1.0000x reference)
#include <cuda_runtime.h>
#include <cuda_fp16.h>
#include <cstdint>

// ---------------------------------------------------------------------------
// GNN_EBM reduced form:
//   out[b] = MLP_T(c100 * r0[b]) + MLP_Y(c101 * r0[b]),
//   r0 = relu(z @ Win^T + bin),  z = [x|t|y], c_i from sigmoid(B)*mask rowsums.
//
// Round-15: SINGLE kernel. Grid=128 blocks (all co-resident on 148 SMs), so
// prep (fragment packing + c_s rows) is distributed across blocks and
// separated from compute by a sense-reversing device-wide spin barrier.
// Phase-2 compute path is identical to R11 (best measured).
// ---------------------------------------------------------------------------

#define DX      100
#define DN      102
#define HID     256
#define MH      128
#define BT      16             // batch rows per block
#define NBLK    128
#define BATCH   2048
#define THREADS 1024
#define NCA     7              // stage-A chunks (16 k each)
#define NCB     16             // stage-B chunks

#define ZSW     60             // z row stride in 4B words (conflict-free ldsm)
#define RSW     132            // r0 row stride in words  (conflict-free ldsm)

#define NFRAG_A (32 * NCA * 32)     // 7168
#define NFRAG_B (32 * NCB * 32)     // 16384
#define NFRAG   (NFRAG_A + NFRAG_B) // 23552 = 128 * 184
#define FPB     (NFRAG / NBLK)      // 184 fragments per block

__device__ float g_c_s[DN];                          // s[j] = rowsum_j(A)/N
__device__ __align__(16) uint2 g_fA[NFRAG_A];        // [tile][chunk][lane]
__device__ __align__(16) uint2 g_fB[NFRAG_B];        // [br*16+wb][chunk][lane]
__device__ int g_bar_cnt  = 0;                       // barrier arrivals
__device__ int g_bar_sense = 0;                      // sense flag (toggles/launch)

__device__ __forceinline__ float sigm(float v) {
    return 1.0f / (1.0f + __expf(-v));
}

__device__ __forceinline__ void mma16(float* c, const uint32_t* a,
                                      uint32_t b0, uint32_t b1) {
    asm volatile(
        "mma.sync.aligned.m16n8k16.row.col.f32.f16.f16.f32 "
        "{%0,%1,%2,%3},{%4,%5,%6,%7},{%8,%9},{%0,%1,%2,%3};"
        : "+f"(c[0]), "+f"(c[1]), "+f"(c[2]), "+f"(c[3])
        : "r"(a[0]), "r"(a[1]), "r"(a[2]), "r"(a[3]), "r"(b0), "r"(b1));
}

__device__ __forceinline__ void ldsm4(uint32_t* r, uint32_t saddr) {
    asm volatile(
        "ldmatrix.sync.aligned.m8n8.x4.shared.b16 {%0,%1,%2,%3}, [%4];"
        : "=r"(r[0]), "=r"(r[1]), "=r"(r[2]), "=r"(r[3]) : "r"(saddr));
}

__device__ __forceinline__ uint32_t smem_u32(const void* p) {
    return (uint32_t)__cvta_generic_to_shared(p);
}

__device__ __forceinline__ uint32_t pack_h2(float v0, float v1) {
    __half2 h = __floats2half2_rn(v0, v1);   // cvt.rn.f16x2.f32
    return *reinterpret_cast<uint32_t*>(&h);
}

// ---------------------------------------------------------------------------
// Fused single kernel: 128 blocks x 1024 threads (all co-resident).
// ---------------------------------------------------------------------------
__global__ __launch_bounds__(THREADS, 1) void fused_kernel(
    const float* __restrict__ x,   const float* __restrict__ tt,
    const float* __restrict__ yy,  const float* __restrict__ bin,
    const float* __restrict__ Win, const float* __restrict__ WT1,
    const float* __restrict__ WY1,
    const float* __restrict__ bT1, const float* __restrict__ wT2,
    const float* __restrict__ bY1, const float* __restrict__ wY2,
    const float* __restrict__ bT2, const float* __restrict__ bY2,
    const float* __restrict__ Bp,
    float* __restrict__ out)
{
    __shared__ __align__(16) uint32_t zh[BT * ZSW];
    __shared__ __align__(16) uint32_t r0h[BT * RSW];
    __shared__ float wsum[4];
    __shared__ float accc[2];

    const int t    = threadIdx.x;
    const int w    = t >> 5;
    const int lane = t & 31;
    const int grp  = lane >> 2;
    const int qid  = lane & 3;
    const int bid  = blockIdx.x;
    const int b0   = bid * BT;

    const int brB = w >> 4;       // stage-B branch (0=T, 1=Y)
    const int wb_ = w & 15;

    // read barrier sense BEFORE arriving (flip can only happen after ALL
    // blocks arrive, hence after this read)
    const int sense0 = *(volatile int*)&g_bar_sense;

    if (t < 2) accc[t] = 0.0f;

    // ---- phase 0: out prefill (own rows; block-internal ordering) ----
    if (t < BT)
        out[b0 + t] = bT2[0] + bY2[0];

    // ---- phase 0: z-fill (one element per thread; 960 < 1024) ----
    if (t < BT * ZSW) {
        int r  = t / ZSW;
        int kw = t - r * ZSW;
        int b  = b0 + r;
        float v0 = 0.0f, v1 = 0.0f;
        int k0 = 2 * kw;
        if (k0 < DX)            v0 = x[b * DX + k0];
        else if (k0 == DX)      v0 = tt[b];
        else if (k0 == DX + 1)  v0 = yy[b];
        int k1 = k0 + 1;
        if (k1 < DX)            v1 = x[b * DX + k1];
        else if (k1 == DX)      v1 = tt[b];
        else if (k1 == DX + 1)  v1 = yy[b];
        zh[t] = pack_h2(v0, v1);
    }

    // ---- phase 1a: pack this block's 184 weight fragments ----
    if (t < FPB) {
        int fid = bid * FPB + t;
        if (fid < NFRAG_A) {
            int nt   = fid / (NCA * 32);
            int rem  = fid - nt * (NCA * 32);
            int g    = rem >> 5;
            int ln   = rem & 31;
            int h  = 8 * nt + (ln >> 2);
            int k0 = 16 * g + 2 * (ln & 3);
            const float* wr = Win + h * DN;
            float v0 = (k0     < DN) ? wr[k0]     : 0.0f;
            float v1 = (k0 + 1 < DN) ? wr[k0 + 1] : 0.0f;
            float v2 = (k0 + 8 < DN) ? wr[k0 + 8] : 0.0f;
            float v3 = (k0 + 9 < DN) ? wr[k0 + 9] : 0.0f;
            uint2 o;
            o.x = pack_h2(v0, v1);
            o.y = pack_h2(v2, v3);
            g_fA[fid] = o;
        } else {
            int fid2 = fid - NFRAG_A;
            int tile = fid2 / (NCB * 32);   // br*16 + wb
            int rem  = fid2 - tile * (NCB * 32);
            int j    = rem >> 5;
            int ln   = rem & 31;
            const float* W = (tile >> 4) ? WY1 : WT1;
            int h  = 8 * (tile & 15) + (ln >> 2);
            int k0 = 16 * j + 2 * (ln & 3);
            const float* wr = W + h * HID;
            uint2 o;
            o.x = pack_h2(wr[k0],     wr[k0 + 1]);
            o.y = pack_h2(wr[k0 + 8], wr[k0 + 9]);
            g_fB[fid2] = o;
        }
    }

    // ---- phase 1b: blocks 0..101 compute one g_c_s row each ----
    if (bid < DN && t < 128) {
        int k = t;
        float v = 0.0f;
        bool valid = (bid == DN - 1) ? (k == DN - 2) : (k < DN && k != bid);
        if (valid) v = sigm(Bp[bid * DN + k]);
        #pragma unroll
        for (int off = 16; off > 0; off >>= 1)
            v += __shfl_xor_sync(0xFFFFFFFFu, v, off);
        if ((t & 31) == 0) wsum[t >> 5] = v;
    }
    __syncthreads();
    if (bid < DN && t == 0)
        g_c_s[bid] = (wsum[0] + wsum[1] + wsum[2] + wsum[3]) / (float)DN;

    // ---- device-wide barrier (sense-reversing; all CTAs co-resident) ----
    __threadfence();     // make this thread's global writes visible
    __syncthreads();     // all threads of block fenced
    if (t == 0) {
        int arrived = atomicAdd(&g_bar_cnt, 1);
        if (arrived == NBLK - 1) {
            g_bar_cnt = 0;
            __threadfence();
            atomicExch(&g_bar_sense, sense0 ^ 1);
        } else {
            while (atomicAdd(&g_bar_sense, 0) == sense0)
                __nanosleep(64);
        }
    }
    __syncthreads();     // whole block past barrier; z tile + accc also ready

    // ---- c partial sums: per-warp shfl reduce + 1 atomic/warp ----
    if (w < 4) {
        int j = t;   // 0..127
        float v = 0.0f;
        if (j < DN && j != DN - 2)
            v = sigm(Bp[(DN - 2) * DN + j]) * (1.0f + g_c_s[j]);
        #pragma unroll
        for (int off = 16; off > 0; off >>= 1)
            v += __shfl_xor_sync(0xFFFFFFFFu, v, off);
        if (lane == 0) atomicAdd(&accc[0], v);
        if (t == 0)
            atomicAdd(&accc[1],
                      sigm(Bp[(DN - 1) * DN + (DN - 2)]) * (1.0f + g_c_s[DN - 2]));
    }

    // ---- hoist stage-A weights into registers (7 x uint2) ----
    uint2 wA[NCA];
    {
        const uint2* fA = g_fA + (w * NCA) * 32 + lane;
        #pragma unroll
        for (int g = 0; g < NCA; g++) wA[g] = __ldg(fA + g * 32);
    }

    // ldmatrix per-lane source addresses
    const int arow = lane & 15;
    const int acol = (lane >> 4) * 4;
    const uint32_t zh_a  = smem_u32(zh)  + (arow * ZSW + acol) * 4;
    const uint32_t r0h_a = smem_u32(r0h) + (arow * RSW + acol) * 4;

    float accM[4], acc2[4];
    #pragma unroll
    for (int i = 0; i < 4; i++) { accM[i] = 0.0f; acc2[i] = 0.0f; }

    // ---- stage A: 7 chunks, ping-pong ldsm, dual accumulators ----
    {
        uint32_t fa[4], fb[4];
        ldsm4(fa, zh_a);
        #pragma unroll
        for (int g = 0; g < NCA; g++) {
            uint32_t* cur = (g & 1) ? fb : fa;
            uint32_t* nxt = (g & 1) ? fa : fb;
            if (g + 1 < NCA) ldsm4(nxt, zh_a + (g + 1) * 32);
            mma16((g & 1) ? acc2 : accM, cur, wA[g].x, wA[g].y);
        }
    }

    // ---- stage-B weights: rolling prefetch, distance 4 ----
    const uint2* fB = g_fB + ((brB * 16 + wb_) * NCB) * 32 + lane;
    uint2 wB[NCB];   // fully unrolled below -> ~5 live
    #pragma unroll
    for (int j = 0; j < 4; j++) wB[j] = __ldg(fB + j * 32);

    // stage-A epilogue: bias, relu, pack -> r0h
    {
        int h0 = 8 * w + 2 * qid;
        float bi0 = bin[h0], bi1 = bin[h0 + 1];
        float v00 = fmaxf(accM[0] + acc2[0] + bi0, 0.0f);
        float v01 = fmaxf(accM[1] + acc2[1] + bi1, 0.0f);
        float v10 = fmaxf(accM[2] + acc2[2] + bi0, 0.0f);
        float v11 = fmaxf(accM[3] + acc2[3] + bi1, 0.0f);
        int wofs = 4 * w + qid;
        r0h[grp * RSW + wofs]       = pack_h2(v00, v01);
        r0h[(grp + 8) * RSW + wofs] = pack_h2(v10, v11);
    }

    __syncthreads();   // r0 handoff (also orders accc atomics)

    #pragma unroll
    for (int i = 0; i < 4; i++) { accM[i] = 0.0f; acc2[i] = 0.0f; }

    // ---- stage B: 16 chunks, ping-pong ldsm, rolling weight prefetch ----
    {
        uint32_t fa[4], fb[4];
        ldsm4(fa, r0h_a);
        #pragma unroll
        for (int j = 0; j < NCB; j++) {
            if (j + 4 < NCB) wB[j + 4] = __ldg(fB + (j + 4) * 32);
            uint32_t* cur = (j & 1) ? fb : fa;
            uint32_t* nxt = (j & 1) ? fa : fb;
            if (j + 1 < NCB) ldsm4(nxt, r0h_a + (j + 1) * 32);
            mma16((j & 1) ? acc2 : accM, cur, wB[j].x, wB[j].y);
        }
    }

    // ---- stage-B epilogue: c-scale, bias, relu, dot w2, direct atomics ----
    {
        const float* b1p = brB ? bY1 : bT1;
        const float* w2p = brB ? wY2 : wT2;
        const float  cs  = 1.0f + g_c_s[DN - 2 + brB] + accc[brB] / (float)DN;

        int h0 = 8 * wb_ + 2 * qid;
        float b10 = b1p[h0], b11 = b1p[h0 + 1];
        float w20 = w2p[h0], w21 = w2p[h0 + 1];
        float m, sl = 0.0f, sh = 0.0f;
        m = fmaxf(fmaf(cs, accM[0] + acc2[0], b10), 0.0f); sl = fmaf(m, w20, sl);
        m = fmaxf(fmaf(cs, accM[1] + acc2[1], b11), 0.0f); sl = fmaf(m, w21, sl);
        m = fmaxf(fmaf(cs, accM[2] + acc2[2], b10), 0.0f); sh = fmaf(m, w20, sh);
        m = fmaxf(fmaf(cs, accM[3] + acc2[3], b11), 0.0f); sh = fmaf(m, w21, sh);
        sl += __shfl_xor_sync(0xFFFFFFFFu, sl, 1);
        sl += __shfl_xor_sync(0xFFFFFFFFu, sl, 2);
        sh += __shfl_xor_sync(0xFFFFFFFFu, sh, 1);
        sh += __shfl_xor_sync(0xFFFFFFFFu, sh, 2);
        if (qid == 0) {
            atomicAdd(out + b0 + grp,     sl);   // out prefilled with bT2+bY2
            atomicAdd(out + b0 + grp + 8, sh);
        }
    }
}

// ---------------------------------------------------------------------------
extern "C" void kernel_launch(void* const* d_in, const int* in_sizes, int n_in,
                              void* d_out, int out_size)
{
    const float* x    = (const float*)d_in[0];
    const float* tt   = (const float*)d_in[1];
    const float* yy   = (const float*)d_in[2];
    const float* Bprm = (const float*)d_in[3];
    const float* Win  = (const float*)d_in[4];
    const float* bin  = (const float*)d_in[5];
    const float* WT1  = (const float*)d_in[6];
    const float* bT1  = (const float*)d_in[7];
    const float* wT2  = (const float*)d_in[8];
    const float* bT2  = (const float*)d_in[9];
    const float* WY1  = (const float*)d_in[10];
    const float* bY1  = (const float*)d_in[11];
    const float* wY2  = (const float*)d_in[12];
    const float* bY2  = (const float*)d_in[13];
    float* out = (float*)d_out;

    fused_kernel<<<NBLK, THREADS>>>(
        x, tt, yy, bin,
        Win, WT1, WY1,
        bT1, wT2,
        bY1, wY2, bT2, bY2, Bprm, out);
}